// round 5
// baseline (speedup 1.0000x reference)
#include <cuda_runtime.h>
#include <cuda_bf16.h>
#include <cstdint>

#define B_ 128
#define T_ 4096
#define F_ 64
#define H_ 128
#define G_ 512   /* 4*H */

// Scratch: precomputed input gates xg[b][t][512] = X[b,t,:]@W_ih^T + b_ih + b_hh
__device__ float g_xg[268435456ull];   // 1 GiB

// ---------------- f32x2 helpers (packed fp32: 2x FFMA throughput) ----------
__device__ __forceinline__ unsigned long long packf2(float x, float y) {
    unsigned long long r;
    asm("mov.b64 %0, {%1, %2};" : "=l"(r) : "f"(x), "f"(y));
    return r;
}
__device__ __forceinline__ float2 unpackf2(unsigned long long v) {
    float2 r;
    asm("mov.b64 {%0, %1}, %2;" : "=f"(r.x), "=f"(r.y) : "l"(v));
    return r;
}
__device__ __forceinline__ unsigned long long ffma2(unsigned long long a,
                                                    unsigned long long b,
                                                    unsigned long long c) {
    unsigned long long d;
    asm("fma.rn.f32x2 %0, %1, %2, %3;" : "=l"(d) : "l"(a), "l"(b), "l"(c));
    return d;
}

__device__ __forceinline__ float sigmoidf_(float x) {
    return __fdividef(1.0f, 1.0f + __expf(-x));
}
__device__ __forceinline__ float tanhf_(float x) {
    float ax = fabsf(x);
    float e  = __expf(-2.0f * ax);           // e in (0,1], never overflows
    float t  = __fdividef(1.0f - e, 1.0f + e);
    return copysignf(t, x);
}

// ---------------------------------------------------------------------------
// Kernel 1: xg[b][t][j] = sum_f X[b][t][f] * W_ih[j][f] + b_ih[j] + b_hh[j]
// ---------------------------------------------------------------------------
__global__ __launch_bounds__(256) void xg_kernel(
    const float* __restrict__ X,
    const float* __restrict__ W_ih,
    const float* __restrict__ b_ih,
    const float* __restrict__ b_hh)
{
    extern __shared__ float smem[];
    float* sW = smem;                 // 512 x 65 (pad 1)
    float* sX = smem + 512 * 65;      // 64 x 64

    const int t  = threadIdx.x;
    const int b  = blockIdx.y;
    const int t0 = blockIdx.x * 64;

    for (int idx = t; idx < 512 * 64; idx += 256) {
        int j = idx >> 6, k = idx & 63;
        sW[j * 65 + k] = W_ih[idx];
    }
    const float* Xb = X + ((size_t)b * T_ + t0) * F_;
    for (int idx = t; idx < 64 * 64; idx += 256) sX[idx] = Xb[idx];
    __syncthreads();

    const int r0 = t, r1 = t + 256;

    unsigned long long wpA[32], wpB[32];
#pragma unroll
    for (int p = 0; p < 32; ++p) {
        wpA[p] = packf2(sW[r0 * 65 + 2 * p], sW[r0 * 65 + 2 * p + 1]);
        wpB[p] = packf2(sW[r1 * 65 + 2 * p], sW[r1 * 65 + 2 * p + 1]);
    }
    const float biasA = __ldg(b_ih + r0) + __ldg(b_hh + r0);
    const float biasB = __ldg(b_ih + r1) + __ldg(b_hh + r1);

    float* outb = g_xg + ((size_t)b * T_ + t0) * G_;

    for (int tt = 0; tt < 64; ++tt) {
        const float4* x4 = (const float4*)(sX + tt * 64);
        unsigned long long aA0 = 0, aA1 = 0, aB0 = 0, aB1 = 0;
#pragma unroll
        for (int q = 0; q < 16; ++q) {
            float4 v = x4[q];
            unsigned long long h01 = packf2(v.x, v.y);
            unsigned long long h23 = packf2(v.z, v.w);
            aA0 = ffma2(wpA[2 * q],     h01, aA0);
            aA1 = ffma2(wpA[2 * q + 1], h23, aA1);
            aB0 = ffma2(wpB[2 * q],     h01, aB0);
            aB1 = ffma2(wpB[2 * q + 1], h23, aB1);
        }
        float2 u0 = unpackf2(aA0), u1 = unpackf2(aA1);
        float2 v0 = unpackf2(aB0), v1 = unpackf2(aB1);
        outb[(size_t)tt * G_ + r0] = (u0.x + u0.y) + (u1.x + u1.y) + biasA;
        outb[(size_t)tt * G_ + r1] = (v0.x + v0.y) + (v1.x + v1.y) + biasB;
    }
}

// ---------------------------------------------------------------------------
// Kernel 2: persistent recurrent LSTM. One CTA per batch row, 256 threads.
// Lane-pair row assignment (r = t>>1):
//   even t: rows (i_r, f_r), owns c_r
//   odd  t: rows (g_r, o_r), owns h_r
// c/h update exchanged via shfl_xor(1) -> only ONE barrier per step.
// W_hh k=0..95 in fp32 registers; k=96..127 streamed fp32 from shared.
// h double-buffered in shared, read as ulonglong2 (direct f32x2 operands).
// ---------------------------------------------------------------------------
__global__ __launch_bounds__(256, 1) void lstm_kernel(
    const float* __restrict__ W_hh,
    float* __restrict__ out)
{
    extern __shared__ float dsm[];
    float* sh_h = dsm;                               // [2][128], 16B aligned
    ulonglong2* swf = (ulonglong2*)(dsm + 256);      // [16][256]

    const int t = threadIdx.x;
    const int b = blockIdx.x;
    const int r = t >> 1;
    const bool odd = (t & 1) != 0;
    const int rowA = odd ? (256 + r) : r;            // g_r : i_r
    const int rowB = odd ? (384 + r) : (128 + r);    // o_r : f_r

    const float* WA = W_hh + (size_t)rowA * H_;
    const float* WB = W_hh + (size_t)rowB * H_;

    // k = 0..95 in registers as f32x2 pairs (192 regs)
    unsigned long long wpA[48], wpB[48];
#pragma unroll
    for (int q = 0; q < 24; ++q) {
        float4 a = __ldg((const float4*)(WA + 4 * q));
        wpA[2 * q]     = packf2(a.x, a.y);
        wpA[2 * q + 1] = packf2(a.z, a.w);
        float4 c4 = __ldg((const float4*)(WB + 4 * q));
        wpB[2 * q]     = packf2(c4.x, c4.y);
        wpB[2 * q + 1] = packf2(c4.z, c4.w);
    }
    // k = 96..127 streamed, fp32 in shared, lane-major (conflict-free)
#pragma unroll
    for (int v = 0; v < 8; ++v) {
        float4 a  = __ldg((const float4*)(WA + 96 + 4 * v));
        float4 c4 = __ldg((const float4*)(WB + 96 + 4 * v));
        swf[v * 256 + t]       = *(const ulonglong2*)&a;
        swf[(8 + v) * 256 + t] = *(const ulonglong2*)&c4;
    }
    sh_h[t] = 0.0f;                                   // zero both h buffers
    __syncthreads();

    const float* xb = g_xg + (size_t)b * T_ * G_;
    const float* pA = xb + rowA;
    const float* pB = xb + rowB;
    float xgA = __ldg(pA);
    float xgB = __ldg(pB);

    float c = 0.0f;
    float h_out = 0.0f;
    const ulonglong2* swfc = swf;

    for (int ts = 0; ts < T_; ++ts) {
        const int inc = (ts < T_ - 1) ? G_ : 0;
        float nxA = __ldg(pA + inc);                  // next-step xg prefetch
        float nxB = __ldg(pB + inc);

        const ulonglong2* hv = (const ulonglong2*)(sh_h + ((ts & 1) << 7));
        unsigned long long aA0 = 0, aA1 = 0, aB0 = 0, aB1 = 0;
#pragma unroll
        for (int q = 0; q < 24; ++q) {                // k=0..95, register W
            ulonglong2 hq = hv[q];                    // broadcast LDS.128
            aA0 = ffma2(wpA[2 * q],     hq.x, aA0);
            aA1 = ffma2(wpA[2 * q + 1], hq.y, aA1);
            aB0 = ffma2(wpB[2 * q],     hq.x, aB0);
            aB1 = ffma2(wpB[2 * q + 1], hq.y, aB1);
        }
#pragma unroll
        for (int v = 0; v < 8; ++v) {                 // k=96..127, streamed W
            ulonglong2 hq = hv[24 + v];
            ulonglong2 wA = swfc[v * 256 + t];
            ulonglong2 wB = swfc[(8 + v) * 256 + t];
            aA0 = ffma2(wA.x, hq.x, aA0);
            aA1 = ffma2(wA.y, hq.y, aA1);
            aB0 = ffma2(wB.x, hq.x, aB0);
            aB1 = ffma2(wB.y, hq.y, aB1);
        }
        float2 u0 = unpackf2(aA0), u1 = unpackf2(aA1);
        float2 w0 = unpackf2(aB0), w1 = unpackf2(aB1);
        float gA = (u0.x + u0.y) + (u1.x + u1.y) + xgA;
        float gB = (w0.x + w0.y) + (w1.x + w1.y) + xgB;

        // even: a=sig(i), bb=sig(f)   odd: a=tanh(g), bb=sig(o)
        float a  = odd ? tanhf_(gA) : sigmoidf_(gA);
        float bb = sigmoidf_(gB);
        float aX = __shfl_xor_sync(0xFFFFFFFFu, a, 1);
        float tc = 0.0f;
        if (!odd) {                                   // c = f*c + i*g
            c = fmaf(bb, c, a * aX);
            tc = tanhf_(c);
        }
        float tcX = __shfl_xor_sync(0xFFFFFFFFu, tc, 1);
        if (odd) {                                    // h = o * tanh(c)
            float h = bb * tcX;
            sh_h[(((ts + 1) & 1) << 7) + r] = h;      // write other buffer
            h_out = h;
        }

        pA += inc; pB += inc;
        xgA = nxA; xgB = nxB;
        __syncthreads();                              // h visible for next step
    }

    if (odd) out[(size_t)b * H_ + r] = h_out;
}

// ---------------------------------------------------------------------------
extern "C" void kernel_launch(void* const* d_in, const int* in_sizes, int n_in,
                              void* d_out, int out_size)
{
    const float* X    = (const float*)d_in[0];   // [128,4096,64]
    const float* W_ih = (const float*)d_in[1];   // [512,64]
    const float* W_hh = (const float*)d_in[2];   // [512,128]
    const float* b_ih = (const float*)d_in[3];   // [512]
    const float* b_hh = (const float*)d_in[4];   // [512]
    float* out = (float*)d_out;                  // [128,128]

    size_t smem1 = (size_t)(512 * 65 + 64 * 64) * sizeof(float);  // ~146 KB
    cudaFuncSetAttribute(xg_kernel,
                         cudaFuncAttributeMaxDynamicSharedMemorySize, (int)smem1);

    size_t smem2 = 256 * sizeof(float) + 16 * 256 * sizeof(ulonglong2); // 66.5 KB
    cudaFuncSetAttribute(lstm_kernel,
                         cudaFuncAttributeMaxDynamicSharedMemorySize, (int)smem2);

    dim3 g1(T_ / 64, B_);
    xg_kernel<<<g1, 256, smem1>>>(X, W_ih, b_ih, b_hh);
    lstm_kernel<<<B_, 256, smem2>>>(W_hh, out);
}